// round 17
// baseline (speedup 1.0000x reference)
#include <cuda_runtime.h>
#include <cuda_bf16.h>
#include <math.h>

#define BATCH 2
#define HH    120
#define WW    160
#define PLANE (HH*WW)
#define NP    (BATCH*PLANE)

// ---------------- scratch ---------------------------------------------------
__device__ float g_cd [BATCH*16 *PLANE];
__device__ float g_bst[NP];
__device__ float g_bsp[NP];
__device__ float g_t1 [BATCH*128*PLANE];
__device__ float g_t2 [BATCH*128*PLANE];
__device__ float g_dd [BATCH*256*PLANE];
__device__ float g_ha [BATCH*128*PLANE];
__device__ float g_hb [BATCH*128*PLANE];
__device__ float g_zb [BATCH*128*PLANE];
__device__ float g_rb [BATCH*128*PLANE];
__device__ float g_pb [BATCH*16 *PLANE];
// transposed weights for FFMA convs (needs 856064 floats)
__device__ __align__(16) float g_wt[860000];
#define OFF_E1  0
#define OFF_E2  100352
#define OFF_E3  247808
#define OFF_E4  395264
#define OFF_P1  690176
#define OFF_P2  837632
// prepacked bf16 GRU weights: 6 sections x 45 chunks x 2 parts x (128 x 72)
#define WA2 829440
__device__ __align__(16) __nv_bfloat16 g_wa[6*WA2];

// ---------------- helpers ---------------------------------------------------
__device__ __forceinline__ unsigned long long fma2(unsigned long long a,
                                                   unsigned long long b,
                                                   unsigned long long c) {
    unsigned long long d;
    asm("fma.rn.f32x2 %0, %1, %2, %3;" : "=l"(d) : "l"(a), "l"(b), "l"(c));
    return d;
}
__device__ __forceinline__ unsigned long long splat2(float x) {
    unsigned long long d;
    asm("mov.b64 %0, {%1, %1};" : "=l"(d) : "f"(x));
    return d;
}
__device__ __forceinline__ float lo32(unsigned long long v) {
    return __uint_as_float((unsigned)(v & 0xffffffffull));
}
__device__ __forceinline__ float hi32(unsigned long long v) {
    return __uint_as_float((unsigned)(v >> 32));
}
__device__ __forceinline__ unsigned smaddr(const void* p) {
    return (unsigned)__cvta_generic_to_shared(p);
}
__device__ __forceinline__ void cpa4(unsigned d, const void* s, int sz) {
    asm volatile("cp.async.ca.shared.global [%0], [%1], 4, %2;"
                 :: "r"(d), "l"(s), "r"(sz));
}
__device__ __forceinline__ void cpa16(unsigned d, const void* s, int sz) {
    asm volatile("cp.async.cg.shared.global [%0], [%1], 16, %2;"
                 :: "r"(d), "l"(s), "r"(sz));
}
__device__ __forceinline__ void cpa_commit() {
    asm volatile("cp.async.commit_group;");
}
// mma.sync m16n8k16 bf16 (HMMA; baseline PTX, works on compute_103)
__device__ __forceinline__ void hmma(float* c, const unsigned* a,
                                     unsigned b0, unsigned b1) {
    asm volatile(
        "mma.sync.aligned.m16n8k16.row.col.f32.bf16.bf16.f32 "
        "{%0,%1,%2,%3},{%4,%5,%6,%7},{%8,%9},{%0,%1,%2,%3};"
        : "+f"(c[0]), "+f"(c[1]), "+f"(c[2]), "+f"(c[3])
        : "r"(a[0]), "r"(a[1]), "r"(a[2]), "r"(a[3]), "r"(b0), "r"(b1));
}
__device__ __forceinline__ unsigned short bfbits(__nv_bfloat16 h) {
    return *(unsigned short*)&h;
}

// ---------------- weight transpose (FFMA path) ------------------------------
__global__ void transp_k(const float* __restrict__ src, float* __restrict__ dst,
                         int Cout, int Cin, int KK)
{
    const int idx = blockIdx.x * blockDim.x + threadIdx.x;
    const int total = Cout * Cin * KK;
    if (idx >= total) return;
    const int co  = idx / (Cin * KK);
    const int rem = idx - co * (Cin * KK);
    dst[(size_t)rem * Cout + co] = src[idx];
}

// ---------------- bf16 hi/lo prepack for GRU mma ----------------------------
// chunk c2 = cc*5 + t; per chunk: [part0: 128 rows x 72 bf16][part1 same]
__global__ void prep2(const float* __restrict__ W, __nv_bfloat16* __restrict__ dst)
{
    const int idx = blockIdx.x * blockDim.x + threadIdx.x;
    if (idx >= 45 * 128 * 72) return;
    const int c2  = idx / (128 * 72);
    const int rem = idx - c2 * (128 * 72);
    const int co  = rem / 72;
    const int kk  = rem - co * 72;
    const int cc = c2 / 5, t = c2 % 5;
    float v = 0.f;
    if (kk < 64) v = W[((size_t)co * 576 + (cc * 64 + kk)) * 5 + t];
    const __nv_bfloat16 hi = __float2bfloat16_rn(v);
    const __nv_bfloat16 lo = __float2bfloat16_rn(v - __bfloat162float(hi));
    dst[(size_t)c2 * 18432 + co * 72 + kk]        = hi;
    dst[(size_t)c2 * 18432 + 9216 + co * 72 + kk] = lo;
}

// ---------------- mma.sync GRU conv -----------------------------------------
// One CTA = (row y, cotile, batch). D[128co,160px] = sum_{5 taps x 576 ci}.
// 8 warps: wm=wid&3 (32 co), wn=wid>>2 (80 px); warp tile 2x10 m16n8k16.
// bf16 split, 3 products. VERT: taps along y. MODE 0 = z|r pair (cot picks),
// MODE 1 = q blend.
#define SM_X 0
#define SM_A 42240
#define SM_B 79104
#define SM_MMA 125184

template<int VERT, int MODE>
__global__ __launch_bounds__(256)
void mma_conv(const float* __restrict__ in0, const float* __restrict__ in1,
              const float* __restrict__ in2,
              const __nv_bfloat16* __restrict__ waA,
              const __nv_bfloat16* __restrict__ waB,
              const float* __restrict__ biasA, const float* __restrict__ biasB,
              const float* __restrict__ hg, const float* __restrict__ zbuf,
              float* __restrict__ outA, float* __restrict__ outB)
{
    extern __shared__ __align__(16) char smem[];
    const unsigned sb = smaddr(smem);
    const int tid  = threadIdx.x;
    const int wid  = tid >> 5;
    const int lane = tid & 31;
    const int y    = blockIdx.x;
    const int cot  = blockIdx.y;
    const int b    = blockIdx.z;

    const __nv_bfloat16* wa = (MODE == 0 && cot == 1) ? waB : waA;
    const float* bias       = (MODE == 0 && cot == 1) ? biasB : biasA;
    float* outp             = (MODE == 0 && cot == 1) ? outB : outA;

    const int wm = wid & 3, wn = wid >> 2;
    const int g = lane >> 2, tq = lane & 3;

    float acc[2][10][4];
#pragma unroll
    for (int mt = 0; mt < 2; mt++)
#pragma unroll
        for (int nt = 0; nt < 10; nt++)
#pragma unroll
            for (int i = 0; i < 4; i++) acc[mt][nt][i] = 0.f;

    for (int k = 0; k < 45; k++) {
        const int cc = k / 5, t = k % 5;
        __syncthreads();   // previous chunk fully consumed
        // ---- stage A (both parts, contiguous 36864B) ----
        {
            const char* asrc = (const char*)(wa + (size_t)k * 18432);
            for (int i = tid; i < 2304; i += 256)
                cpa16(sb + SM_A + i * 16, asrc + i * 16, 16);
        }
        // ---- stage X floats when needed ----
        if (VERT || t == 0) {
            const float* src; int ct, cl;
            if (cc < 2)      { src = in0; ct = 128; cl = cc * 64; }
            else if (cc < 6) { src = in1; ct = 256; cl = (cc - 2) * 64; }
            else             { src = in2; ct = 192; cl = (cc - 6) * 64; }
            const float* sbase = src + ((size_t)b * ct + cl) * PLANE;
            const int yy = VERT ? (y + t - 2) : y;
            const bool yok = (yy >= 0 && yy < HH);
            for (int i = tid; i < 64 * 164; i += 256) {
                const int ci = i / 164, col = i - ci * 164;
                const int xx = VERT ? col : (col - 2);
                const bool ok = yok && xx >= 0 && xx < WW;
                const size_t o = ok ? ((size_t)ci * PLANE + yy * WW + xx) : 0;
                cpa4(sb + SM_X + (unsigned)(ci * 165 + col) * 4, sbase + o, ok ? 4 : 0);
            }
        }
        cpa_commit();
        asm volatile("cp.async.wait_group 0;");
        __syncthreads();
        // ---- build B: [px 160][k 64] bf16 rows stride 144B, hi & lo ----
        {
            const float* sx = (const float*)(smem + SM_X);
            char* bhp = smem + SM_B;
            char* blp = smem + SM_B + 23040;
            for (int i = tid; i < 32 * 160; i += 256) {
                const int kp = i & 31, px = i >> 5;
                const int cx = VERT ? px : (px + t);
                const float v0 = sx[(2 * kp) * 165 + cx];
                const float v1 = sx[(2 * kp + 1) * 165 + cx];
                const __nv_bfloat16 h0 = __float2bfloat16_rn(v0);
                const __nv_bfloat16 h1 = __float2bfloat16_rn(v1);
                const __nv_bfloat16 l0 = __float2bfloat16_rn(v0 - __bfloat162float(h0));
                const __nv_bfloat16 l1 = __float2bfloat16_rn(v1 - __bfloat162float(h1));
                const unsigned hw = (unsigned)bfbits(h0) | ((unsigned)bfbits(h1) << 16);
                const unsigned lw = (unsigned)bfbits(l0) | ((unsigned)bfbits(l1) << 16);
                *(unsigned*)(bhp + px * 144 + kp * 4) = hw;
                *(unsigned*)(blp + px * 144 + kp * 4) = lw;
            }
        }
        __syncthreads();
        // ---- compute: 4 k16 steps ----
        const char* sa  = smem + SM_A;
        const char* sal = smem + SM_A + 18432;
        const char* sbh = smem + SM_B;
        const char* sbl = smem + SM_B + 23040;
#pragma unroll
        for (int st = 0; st < 4; st++) {
            const int kb = st * 32 + tq * 4;   // byte offset of k0 pair
            unsigned Ah[2][4], Al[2][4];
#pragma unroll
            for (int mt = 0; mt < 2; mt++) {
                const int r0 = wm * 32 + mt * 16 + g;
                const char* p = sa + r0 * 144 + kb;
                Ah[mt][0] = *(const unsigned*)p;
                Ah[mt][1] = *(const unsigned*)(p + 8 * 144);
                Ah[mt][2] = *(const unsigned*)(p + 16);
                Ah[mt][3] = *(const unsigned*)(p + 8 * 144 + 16);
                const char* q = sal + r0 * 144 + kb;
                Al[mt][0] = *(const unsigned*)q;
                Al[mt][1] = *(const unsigned*)(q + 8 * 144);
                Al[mt][2] = *(const unsigned*)(q + 16);
                Al[mt][3] = *(const unsigned*)(q + 8 * 144 + 16);
            }
#pragma unroll
            for (int nt = 0; nt < 10; nt++) {
                const int px = wn * 80 + nt * 8 + g;
                const char* pb = sbh + px * 144 + kb;
                const unsigned bh0 = *(const unsigned*)pb;
                const unsigned bh1 = *(const unsigned*)(pb + 16);
                const char* ql = sbl + px * 144 + kb;
                const unsigned bl0 = *(const unsigned*)ql;
                const unsigned bl1 = *(const unsigned*)(ql + 16);
#pragma unroll
                for (int mt = 0; mt < 2; mt++) {
                    hmma(acc[mt][nt], Ah[mt], bh0, bh1);
                    hmma(acc[mt][nt], Al[mt], bh0, bh1);
                    hmma(acc[mt][nt], Ah[mt], bl0, bl1);
                }
            }
        }
    }

    // ---- epilogue ----
#pragma unroll
    for (int mt = 0; mt < 2; mt++) {
#pragma unroll
        for (int half = 0; half < 2; half++) {
            const int row = wm * 32 + mt * 16 + g + half * 8;
            const float bv = bias[row];
            const size_t ro = ((size_t)b * 128 + row) * PLANE + (size_t)y * WW;
#pragma unroll
            for (int nt = 0; nt < 10; nt++) {
                const int px = wn * 80 + nt * 8 + tq * 2;
                const float a0 = acc[mt][nt][half * 2 + 0] + bv;
                const float a1 = acc[mt][nt][half * 2 + 1] + bv;
                float2 o;
                if (MODE == 0) {
                    if (cot == 0) {
                        o.x = 1.f / (1.f + expf(-a0));
                        o.y = 1.f / (1.f + expf(-a1));
                    } else {
                        const float2 h2 = *(const float2*)(hg + ro + px);
                        o.x = h2.x / (1.f + expf(-a0));
                        o.y = h2.y / (1.f + expf(-a1));
                    }
                } else {
                    const float2 z2 = *(const float2*)(zbuf + ro + px);
                    const float2 h2 = *(const float2*)(hg + ro + px);
                    o.x = (1.f - z2.x) * h2.x + z2.x * tanhf(a0);
                    o.y = (1.f - z2.y) * h2.y + z2.y * tanhf(a1);
                }
                *(float2*)(outp + ro + px) = o;
            }
        }
    }
}

// ---------------- FFMA direct conv (encoder/PHead) --------------------------
constexpr int TM = 64, TN = 32;

template<int KH, int KW, int ACT, int MINB>
__global__ __launch_bounds__(128, MINB)
void conv_k(const float* __restrict__ in0,
            const float* __restrict__ wt, const float* __restrict__ bias,
            float* __restrict__ outp, int Cout, int Cin)
{
    constexpr int KK  = KH * KW;
    constexpr int CK  = (KK > 25) ? 1 : 8;
    constexpr int PH  = KH / 2;
    constexpr int PW  = KW / 2;
    constexpr int WIN = 4 + KW - 1;
    constexpr int NW4 = (WIN + 3) / 4;
    constexpr int TNP = 28 + NW4 * 4;
    constexpr int NR  = KH + 1;

    __shared__ __align__(16) float s_w [2][CK * KK * TM];
    __shared__ __align__(16) float s_in[2][CK * NR * TNP];

    const int b      = blockIdx.z;
    const int cotile = blockIdx.y;
    const int tile   = blockIdx.x;
    const int y0     = (tile / (WW / TN)) * 2;
    const int x0     = (tile % (WW / TN)) * TN;
    const int tid = threadIdx.x;
    const int tco = tid >> 3;
    const int tpx = tid & 7;
    const int cob = cotile * TM;

    auto stage = [&](int ci0, int buf) {
        const float* sbp = in0 + ((size_t)b * Cin + ci0) * PLANE;
        for (int i = tid; i < CK * NR * TNP; i += 128) {
            const int ci  = i / (NR * TNP);
            const int rem = i - ci * (NR * TNP);
            const int rr  = rem / TNP;
            const int j   = rem - rr * TNP;
            const int yy  = y0 - PH + rr;
            const int xx  = x0 - PW + j;
            const bool inb = (yy >= 0 && yy < HH && xx >= 0 && xx < WW);
            const size_t o = inb ? ((size_t)ci * PLANE + yy * WW + xx) : 0;
            cpa4(smaddr(&s_in[buf][i]), sbp + o, inb ? 4 : 0);
        }
        for (int i4 = tid; i4 < CK * KK * (TM / 4); i4 += 128) {
            const int co4 = (i4 & 15) * 4;
            const int r   = i4 >> 4;
            const int gco = cob + co4;
            const float* wrow = wt + ((size_t)ci0 * KK + r) * Cout + gco;
            cpa16(smaddr(&s_w[buf][r * TM + co4]), wrow, (gco < Cout) ? 16 : 0);
        }
        cpa_commit();
    };

    unsigned long long acc[2][4][2];
#pragma unroll
    for (int r = 0; r < 2; r++)
#pragma unroll
        for (int i = 0; i < 4; i++) { acc[r][i][0] = 0ull; acc[r][i][1] = 0ull; }

    const int nch = Cin / CK;
    stage(0, 0);
    for (int c = 0; c < nch; c++) {
        if (c + 1 < nch) { stage((c + 1) * CK, (c + 1) & 1);
                           asm volatile("cp.async.wait_group 1;"); }
        else             { asm volatile("cp.async.wait_group 0;"); }
        __syncthreads();
        const float* sw  = s_w [c & 1];
        const float* sin = s_in[c & 1];
        for (int ci = 0; ci < CK; ci++) {
            unsigned long long sp[2][WIN];
            {
                const float* ip = sin + (ci * NR + 0) * TNP + tpx * 4;
                float win[NW4 * 4];
#pragma unroll
                for (int w4 = 0; w4 < NW4; w4++)
                    *(float4*)(win + 4 * w4) = *(const float4*)(ip + 4 * w4);
#pragma unroll
                for (int j = 0; j < WIN; j++) sp[0][j] = splat2(win[j]);
            }
#pragma unroll
            for (int kh = 0; kh < KH; kh++) {
                {
                    const float* ip = sin + (ci * NR + kh + 1) * TNP + tpx * 4;
                    float win[NW4 * 4];
#pragma unroll
                    for (int w4 = 0; w4 < NW4; w4++)
                        *(float4*)(win + 4 * w4) = *(const float4*)(ip + 4 * w4);
#pragma unroll
                    for (int j = 0; j < WIN; j++) sp[(kh + 1) & 1][j] = splat2(win[j]);
                }
                const unsigned long long* s0 = sp[kh & 1];
                const unsigned long long* s1 = sp[(kh + 1) & 1];
#pragma unroll
                for (int kw = 0; kw < KW; kw++) {
                    const ulonglong2 wv = *(const ulonglong2*)
                        (sw + ((ci * KH + kh) * KW + kw) * TM + tco * 4);
#pragma unroll
                    for (int rn = 0; rn < 4; rn++) {
                        acc[0][rn][0] = fma2(wv.x, s0[kw + rn], acc[0][rn][0]);
                        acc[0][rn][1] = fma2(wv.y, s0[kw + rn], acc[0][rn][1]);
                        acc[1][rn][0] = fma2(wv.x, s1[kw + rn], acc[1][rn][0]);
                        acc[1][rn][1] = fma2(wv.y, s1[kw + rn], acc[1][rn][1]);
                    }
                }
            }
        }
        __syncthreads();
    }
#pragma unroll
    for (int row = 0; row < 2; row++) {
        const int y   = y0 + row;
        const int pix = y * WW + x0 + tpx * 4;
#pragma unroll
        for (int rm = 0; rm < 4; rm++) {
            const int co = cob + tco * 4 + rm;
            if (co >= Cout) continue;
            float vv[4];
#pragma unroll
            for (int rn = 0; rn < 4; rn++) {
                const unsigned long long a = acc[row][rn][rm >> 1];
                vv[rn] = (rm & 1) ? hi32(a) : lo32(a);
            }
            const float bv = bias[co];
            float4 o4;
            if (ACT == 1) {
                o4.x = fmaxf(vv[0] + bv, 0.f); o4.y = fmaxf(vv[1] + bv, 0.f);
                o4.z = fmaxf(vv[2] + bv, 0.f); o4.w = fmaxf(vv[3] + bv, 0.f);
            } else {
                o4.x = vv[0] + bv; o4.y = vv[1] + bv;
                o4.z = vv[2] + bv; o4.w = vv[3] + bv;
            }
            *(float4*)(outp + ((size_t)b * Cout + co) * PLANE + pix) = o4;
        }
    }
}

// ---------------- init / epilogue -------------------------------------------
__global__ void init_k(float* __restrict__ cd, float* __restrict__ bst,
                       float* __restrict__ bsp)
{
    const int p = blockIdx.x * blockDim.x + threadIdx.x;
    if (p >= NP) return;
    bst[p] = 0.f; bsp[p] = 5.f;
    const int b = p / PLANE, pp = p - b * PLANE;
    float e = 0.f;
#pragma unroll
    for (int i = 0; i < 16; i++) {
        const float en = e + 5.f;
        cd[((size_t)b * 16 + i) * PLANE + pp] = 0.5f * (e + en);
        e = en;
    }
}
__device__ __forceinline__ float clip80(float v) {
    return fminf(fmaxf(v, 0.f), 80.f);
}
__global__ void epi_k(const float* __restrict__ lg, float* __restrict__ cd,
                      float* __restrict__ bst, float* __restrict__ bsp,
                      float* __restrict__ outp, int iter)
{
    const int p = blockIdx.x * blockDim.x + threadIdx.x;
    if (p >= NP) return;
    const int b = p / PLANE, pp = p - b * PLANE;
    const float* l0 = lg + (size_t)b * 16 * PLANE + pp;
    float*       c0 = cd + (size_t)b * 16 * PLANE + pp;
    float l[16], c[16];
    float m = -1e30f;
#pragma unroll
    for (int i = 0; i < 16; i++) { l[i] = l0[i * PLANE]; m = fmaxf(m, l[i]); }
    float s = 0.f;
#pragma unroll
    for (int i = 0; i < 16; i++) { l[i] = expf(l[i] - m); s += l[i]; }
    const float inv = 1.f / s;
    float dr = 0.f;
#pragma unroll
    for (int i = 0; i < 16; i++) { c[i] = c0[i * PLANE]; dr += l[i] * inv * c[i]; }
    float var = 0.f;
#pragma unroll
    for (int i = 0; i < 16; i++) { const float d = c[i] - dr; var += l[i] * inv * d * d; }
    const float unc = sqrtf(var);
    const float st = bst[p], sp = bsp[p];
    int cnt = 0; float e = st;
#pragma unroll
    for (int i = 1; i <= 15; i++) { e += sp; cnt += (dr >= clip80(e)) ? 1 : 0; }
    e += sp;
    const int label = (dr >= clip80(e)) ? 0 : cnt;
    const float cs = c[label];
    outp[(0 * 6 + iter) * NP + p] = dr;
    outp[(1 * 6 + iter) * NP + p] = cs;
    outp[(2 * 6 + iter) * NP + p] = unc;
    const float nst = fmaxf(dr - 0.5f * unc, 0.f);
    const float nsp = unc * (1.f / 16.f);
    bst[p] = nst; bsp[p] = nsp;
    float ep = clip80(nst), ecur = nst;
#pragma unroll
    for (int i = 0; i < 16; i++) {
        ecur += nsp;
        const float ec = clip80(ecur);
        c0[i * PLANE] = 0.5f * (ep + ec);
        ep = ec;
    }
}

// ---------------- host ------------------------------------------------------
static void do_transp(const float* src, float* dst, int Cout, int Cin, int KK) {
    const int total = Cout * Cin * KK;
    transp_k<<<(total + 255) / 256, 256>>>(src, dst, Cout, Cin, KK);
}

extern "C" void kernel_launch(void* const* d_in, const int* in_sizes, int n_in,
                              void* d_out, int out_size)
{
    (void)in_sizes; (void)n_in; (void)out_size;
    const float* ctx  = (const float*)d_in[1];
    const float* gruh = (const float*)d_in[2];
    const float* w_e1 = (const float*)d_in[3];  const float* b_e1 = (const float*)d_in[4];
    const float* w_e2 = (const float*)d_in[5];  const float* b_e2 = (const float*)d_in[6];
    const float* w_e3 = (const float*)d_in[7];  const float* b_e3 = (const float*)d_in[8];
    const float* w_e4 = (const float*)d_in[9];  const float* b_e4 = (const float*)d_in[10];
    const float* w_z1 = (const float*)d_in[11]; const float* b_z1 = (const float*)d_in[12];
    const float* w_r1 = (const float*)d_in[13]; const float* b_r1 = (const float*)d_in[14];
    const float* w_q1 = (const float*)d_in[15]; const float* b_q1 = (const float*)d_in[16];
    const float* w_z2 = (const float*)d_in[17]; const float* b_z2 = (const float*)d_in[18];
    const float* w_r2 = (const float*)d_in[19]; const float* b_r2 = (const float*)d_in[20];
    const float* w_q2 = (const float*)d_in[21]; const float* b_q2 = (const float*)d_in[22];
    const float* w_p1 = (const float*)d_in[23]; const float* b_p1 = (const float*)d_in[24];
    const float* w_p2 = (const float*)d_in[25]; const float* b_p2 = (const float*)d_in[26];

    float *cd, *bst, *bsp, *t1, *t2, *dd, *ha, *hb, *zb, *rb, *pb, *wt;
    __nv_bfloat16* wa;
    cudaGetSymbolAddress((void**)&cd,  g_cd);
    cudaGetSymbolAddress((void**)&bst, g_bst);
    cudaGetSymbolAddress((void**)&bsp, g_bsp);
    cudaGetSymbolAddress((void**)&t1,  g_t1);
    cudaGetSymbolAddress((void**)&t2,  g_t2);
    cudaGetSymbolAddress((void**)&dd,  g_dd);
    cudaGetSymbolAddress((void**)&ha,  g_ha);
    cudaGetSymbolAddress((void**)&hb,  g_hb);
    cudaGetSymbolAddress((void**)&zb,  g_zb);
    cudaGetSymbolAddress((void**)&rb,  g_rb);
    cudaGetSymbolAddress((void**)&pb,  g_pb);
    cudaGetSymbolAddress((void**)&wt,  g_wt);
    cudaGetSymbolAddress((void**)&wa,  g_wa);
    float* out = (float*)d_out;

    cudaFuncSetAttribute(mma_conv<0,0>, cudaFuncAttributeMaxDynamicSharedMemorySize, SM_MMA);
    cudaFuncSetAttribute(mma_conv<0,1>, cudaFuncAttributeMaxDynamicSharedMemorySize, SM_MMA);
    cudaFuncSetAttribute(mma_conv<1,0>, cudaFuncAttributeMaxDynamicSharedMemorySize, SM_MMA);
    cudaFuncSetAttribute(mma_conv<1,1>, cudaFuncAttributeMaxDynamicSharedMemorySize, SM_MMA);

    do_transp(w_e1, wt + OFF_E1, 128, 16, 49);
    do_transp(w_e2, wt + OFF_E2, 128, 128, 9);
    do_transp(w_e3, wt + OFF_E3, 128, 128, 9);
    do_transp(w_e4, wt + OFF_E4, 256, 128, 9);
    do_transp(w_p1, wt + OFF_P1, 128, 128, 9);
    do_transp(w_p2, wt + OFF_P2, 16, 128, 9);
    const int PG = (45 * 128 * 72 + 255) / 256;
    prep2<<<PG, 256>>>(w_z1, wa + 0 * WA2);
    prep2<<<PG, 256>>>(w_r1, wa + 1 * WA2);
    prep2<<<PG, 256>>>(w_q1, wa + 2 * WA2);
    prep2<<<PG, 256>>>(w_z2, wa + 3 * WA2);
    prep2<<<PG, 256>>>(w_r2, wa + 4 * WA2);
    prep2<<<PG, 256>>>(w_q2, wa + 5 * WA2);

    cudaMemcpyAsync(ha, gruh, sizeof(float) * BATCH * 128 * PLANE,
                    cudaMemcpyDeviceToDevice, 0);
    init_k<<<(NP + 255) / 256, 256>>>(cd, bst, bsp);

    const dim3 g1(300, 1, BATCH), g2(300, 2, BATCH), g4(300, 4, BATCH);
    const dim3 gm2(120, 2, BATCH), gm1(120, 1, BATCH);

    for (int it = 0; it < 6; it++) {
        conv_k<7, 7, 1, 4><<<g2, 128>>>(cd, wt + OFF_E1, b_e1, t1, 128, 16);
        conv_k<3, 3, 1, 5><<<g2, 128>>>(t1, wt + OFF_E2, b_e2, t2, 128, 128);
        conv_k<3, 3, 1, 5><<<g2, 128>>>(t2, wt + OFF_E3, b_e3, t1, 128, 128);
        conv_k<3, 3, 1, 5><<<g4, 128>>>(t1, wt + OFF_E4, b_e4, dd, 256, 128);
        // GRU horizontal: z|r then q (tensor cores via mma.sync)
        mma_conv<0,0><<<gm2, 256, SM_MMA>>>(ha, dd, ctx, wa + 0*WA2, wa + 1*WA2,
                                            b_z1, b_r1, ha, nullptr, zb, rb);
        mma_conv<0,1><<<gm1, 256, SM_MMA>>>(rb, dd, ctx, wa + 2*WA2, nullptr,
                                            b_q1, nullptr, ha, zb, hb, nullptr);
        // GRU vertical
        mma_conv<1,0><<<gm2, 256, SM_MMA>>>(hb, dd, ctx, wa + 3*WA2, wa + 4*WA2,
                                            b_z2, b_r2, hb, nullptr, zb, rb);
        mma_conv<1,1><<<gm1, 256, SM_MMA>>>(rb, dd, ctx, wa + 5*WA2, nullptr,
                                            b_q2, nullptr, hb, zb, ha, nullptr);
        // PHead
        conv_k<3, 3, 1, 5><<<g2, 128>>>(ha, wt + OFF_P1, b_p1, t1, 128, 128);
        conv_k<3, 3, 0, 5><<<g1, 128>>>(t1, wt + OFF_P2, b_p2, pb, 16, 128);
        epi_k<<<(NP + 255) / 256, 256>>>(pb, cd, bst, bsp, out, it);
    }
}